// round 13
// baseline (speedup 1.0000x reference)
#include <cuda_runtime.h>
#include <math.h>

#define SIMS 64
#define SD 65536            // 2^16 state dim
#define PI_F 3.14159265358979323846f
#define INV_SQRT2 0.70710678118654752440f

// ---------------- device scratch (static, no allocation) ----------------
__device__ __align__(16) float2 g_state[SIMS * SD];   // 32 MB (L2-resident)
__device__ float g_partial[SIMS][16][16];             // per-tile Z partials

__device__ __forceinline__ float wsum(float x) {
#pragma unroll
    for (int o = 16; o > 0; o >>= 1) x += __shfl_xor_sync(0xffffffffu, x, o);
    return x;
}

// RY butterfly on register-index bit qb of a 16-entry complex array.
__device__ __forceinline__ void bf_regs(float2 a[16], int qb, float c, float s) {
#pragma unroll
    for (int p = 0; p < 8; p++) {
        const int j0 = ((p >> qb) << (qb + 1)) | (p & ((1 << qb) - 1));
        const int j1 = j0 | (1 << qb);
        const float r0 = c * a[j0].x - s * a[j1].x;
        const float r1 = s * a[j0].x + c * a[j1].x;
        const float i0 = c * a[j0].y - s * a[j1].y;
        const float i1 = s * a[j0].y + c * a[j1].y;
        a[j0].x = r0; a[j1].x = r1; a[j0].y = i0; a[j1].y = i1;
    }
}

// uniform conflict-free swizzle for 8B elements (addr in 8B units, 12 bits)
__device__ __forceinline__ int swz(int a) { return a ^ ((a >> 4) & 15); }

// ======================================================================
// K1: build init product state * D0, RY_A on qubits 0..11 via 3 register
//     residencies (regs=q0..3 -> q4..7 -> q8..11) + 2 CF smem re-partitions.
// addr12 = (q8..11 << 8) | (q4..7 << 4) | (q0..3).  tile = q12..15.
// ======================================================================
__global__ void __launch_bounds__(256) k_pass1(const float* __restrict__ x,
                                               const float* __restrict__ wcrz,
                                               const float* __restrict__ wry,
                                               const float* __restrict__ scale) {
    const int sim = blockIdx.x >> 4;
    const int tile = blockIdx.x & 15;
    const int t = threadIdx.x, lane = t & 31, w = t >> 5;
    __shared__ float2 sbuf[4096];       // 32 KB
    __shared__ float2 A0p[32];          // CRZ L0, controls q0..3 (idx bits = q0..4)
    __shared__ float sc[12], ss[12];    // cos/sin((w_ry0+enc)/2), q0..11
    __shared__ float TL4[16], TM4[16], TH4[16];
    __shared__ float v0[16], v1[16], hw[32];
    __shared__ float THhi;

    if (t < 32) hw[t] = 0.5f * wcrz[t];
    if (t < 16) {
        const int q = t, bb = sim >> 3, p = sim & 7;
        const float xv = x[bb * 128 + (q >> 2) * 32 + p * 4 + (q & 3)];
        const float enc = tanhf(xv * scale[0]) * PI_F;
        float se, ce; sincosf(enc * 0.5f, &se, &ce);
        v0[q] = (ce - se) * INV_SQRT2;   // RY(enc)*H|0>
        v1[q] = (ce + se) * INV_SQRT2;
        if (q < 12) {
            float sA, cA; sincosf((wry[q] + enc) * 0.5f, &sA, &cA);
            sc[q] = cA; ss[q] = sA;
        }
    }
    __syncthreads();
    if (t < 16) {
        float pa = 1.f, pb = 1.f, pc = 1.f;
#pragma unroll
        for (int q = 0; q < 4; q++) {
            pa *= ((t >> q) & 1) ? v1[q]     : v0[q];
            pb *= ((t >> q) & 1) ? v1[4 + q] : v0[4 + q];
            pc *= ((t >> q) & 1) ? v1[8 + q] : v0[8 + q];
        }
        TL4[t] = pa; TM4[t] = pb; TH4[t] = pc;
    }
    if (t == 16) {
        float p = 1.f;
#pragma unroll
        for (int q = 0; q < 4; q++) p *= ((tile >> q) & 1) ? v1[12 + q] : v0[12 + q];
        THhi = p;
    }
    if (t < 32) {   // A0p: controls q0..3, target q+1 (idx bits 0..4 = q0..4)
        float a = 0.f;
#pragma unroll
        for (int q = 0; q < 4; q++)
            if ((t >> q) & 1) a += ((t >> (q + 1)) & 1) ? hw[q] : -hw[q];
        float s, c; sincosf(a, &s, &c);
        A0p[t] = make_float2(c, s);
    }
    // per-thread B0: controls q4..15, targets (q+1)&15. b12 bits 0..11 = q4..15.
    const int M = lane & 15;                 // q4..7 in residency-low
    const int H8 = (lane >> 4) | (w << 1);   // q8..11
    const int b12 = M | (H8 << 4) | (tile << 8);
    float base = 0.f;
#pragma unroll
    for (int q = 4; q < 15; q++)
        if ((b12 >> (q - 4)) & 1) base += ((b12 >> (q - 3)) & 1) ? hw[q] : -hw[q];
    const float w15c = ((b12 >> 11) & 1) ? hw[15] : 0.f;   // control q15, target q0
    float s0, c0, s1, c1;
    sincosf(base - w15c, &s0, &c0);          // q0 = 0
    sincosf(base + w15c, &s1, &c1);          // q0 = 1
    __syncthreads();

    // ---- init amplitudes: residency-low (regs j = q0..3) ----
    const float Kc = TM4[M] * TH4[H8] * THhi;
    const int a0base = (M & 1) << 4;         // q4 bit
    float2 a[16];
#pragma unroll
    for (int j = 0; j < 16; j++) {
        const float2 pa = A0p[j | a0base];
        const float pbx = (j & 1) ? c1 : c0;
        const float pby = (j & 1) ? s1 : s0;
        const float amp = TL4[j] * Kc;
        a[j] = make_float2(amp * (pa.x * pbx - pa.y * pby),
                           amp * (pa.x * pby + pa.y * pbx));
    }
    // qubits 0..3 (regs)
#pragma unroll
    for (int qb = 0; qb < 4; qb++) bf_regs(a, qb, sc[qb], ss[qb]);
    // store residency-low pattern
#pragma unroll
    for (int j = 0; j < 16; j++) sbuf[swz((H8 << 8) | (M << 4) | j)] = a[j];
    __syncthreads();
    // load residency-mid: regs = q4..7; thread: L=lane&15 (q0..3), H8 (q8..11)
    const int L = lane & 15;
#pragma unroll
    for (int m = 0; m < 16; m++) a[m] = sbuf[swz((H8 << 8) | (m << 4) | L)];
#pragma unroll
    for (int qb = 0; qb < 4; qb++) bf_regs(a, qb, sc[4 + qb], ss[4 + qb]);
    // store back to SAME addresses (no barrier needed before this store)
#pragma unroll
    for (int m = 0; m < 16; m++) sbuf[swz((H8 << 8) | (m << 4) | L)] = a[m];
    __syncthreads();
    // load canonical: regs = q8..11; thread t bits = q0..7
#pragma unroll
    for (int h = 0; h < 16; h++) a[h] = sbuf[swz((h << 8) | t)];
#pragma unroll
    for (int qb = 0; qb < 4; qb++) bf_regs(a, qb, sc[8 + qb], ss[8 + qb]);
    float2* st = g_state + sim * SD + (tile << 12);
#pragma unroll
    for (int h = 0; h < 16; h++) st[(h << 8) | t] = a[h];
}

// ======================================================================
// K2: RY_A(12..15), D1 (A1 per-thread + B1 smem), RY_B(12..15).
// Thread bits = q0..11 (low12), regs k = q12..15.
// ======================================================================
__global__ void __launch_bounds__(256) k_pass2(const float* __restrict__ x,
                                               const float* __restrict__ wcrz,
                                               const float* __restrict__ wry,
                                               const float* __restrict__ scale) {
    const int sim = blockIdx.x >> 4;
    const int blk = blockIdx.x & 15;
    const int t = threadIdx.x;
    const int low12 = (blk << 8) | t;
    __shared__ float2 sB1[64];           // [k][q0..1]
    __shared__ float scA[4], ssA[4], scB[4], ssB[4], sw1[16];
    if (t < 16) sw1[t] = 0.5f * wcrz[16 + t];
    if (t < 4) {
        const int q = 12 + t, bb = sim >> 3, p = sim & 7;
        const float xv = x[bb * 128 + 3 * 32 + p * 4 + t];
        const float enc = tanhf(xv * scale[0]) * PI_F;
        float sA, cA; sincosf((wry[q] + enc) * 0.5f, &sA, &cA);
        scA[t] = cA; ssA[t] = sA;
        float sB, cB; sincosf(wry[16 + q] * 0.5f, &sB, &cB);
        scB[t] = cB; ssB[t] = sB;
    }
    __syncthreads();
    // B1 slice: controls q8..15, targets (q+2)&15; idx bits 0..3=q8..11(blk),
    // 4..7=q12..15(k), 8..9=q0..1   (verified in R9)
    if (t < 64) {
        const int k = t >> 2, c2 = t & 3;
        const int i = blk | (k << 4) | (c2 << 8);
        float a = 0.f;
#pragma unroll
        for (int q = 8; q < 16; q++)
            if ((i >> (q - 8)) & 1) a += ((i >> (q - 6)) & 1) ? sw1[q] : -sw1[q];
        float s, c; sincosf(a, &s, &c);
        sB1[t] = make_float2(c, s);
    }
    // A1 per thread: controls q0..7, target q+2 (bits 2..9)
    const int i10 = low12 & 1023;
    float aa = 0.f;
#pragma unroll
    for (int q = 0; q < 8; q++)
        if ((i10 >> q) & 1) aa += ((i10 >> (q + 2)) & 1) ? sw1[q] : -sw1[q];
    float pay, pax; sincosf(aa, &pay, &pax);   // (cos, sin) = (pax, pay)
    __syncthreads();

    float2* st = g_state + sim * SD;
    float2 a[16];
#pragma unroll
    for (int k = 0; k < 16; k++) a[k] = st[(k << 12) | low12];
#pragma unroll
    for (int qb = 0; qb < 4; qb++) bf_regs(a, qb, scA[qb], ssA[qb]);
    const int c2 = t & 3;
#pragma unroll
    for (int k = 0; k < 16; k++) {
        const float2 pb = sB1[(k << 2) | c2];
        const float cr = pax * pb.x - pay * pb.y;
        const float ci = pax * pb.y + pay * pb.x;
        const float nx = a[k].x * cr - a[k].y * ci;
        const float ny = a[k].x * ci + a[k].y * cr;
        a[k] = make_float2(nx, ny);
    }
#pragma unroll
    for (int qb = 0; qb < 4; qb++) bf_regs(a, qb, scB[qb], ssB[qb]);
#pragma unroll
    for (int k = 0; k < 16; k++) st[(k << 12) | low12] = a[k];
}

// ======================================================================
// K3: RY_B qubits 0..11 (reverse residency chain, shuffle-free) + measure.
// Final layout: regs j = q0..3, lane0..3 = q4..7, lane4 = q8, warp = q9..11.
// ======================================================================
__global__ void __launch_bounds__(256) k_pass3(const float* __restrict__ wry) {
    const int sim = blockIdx.x >> 4;
    const int tile = blockIdx.x & 15;
    const int t = threadIdx.x, lane = t & 31, w = t >> 5;
    __shared__ float2 sbuf[4096];
    __shared__ float sc[12], ss[12];
    __shared__ float wred[8][10];
    if (t < 12) {
        float sB, cB; sincosf(wry[16 + t] * 0.5f, &sB, &cB);
        sc[t] = cB; ss[t] = sB;
    }
    __syncthreads();
    const float2* stg = g_state + sim * SD + (tile << 12);
    float2 a[16];
#pragma unroll
    for (int h = 0; h < 16; h++) a[h] = stg[(h << 8) | t];
    // qubits 8..11 (regs, canonical residency)
#pragma unroll
    for (int qb = 0; qb < 4; qb++) bf_regs(a, qb, sc[8 + qb], ss[8 + qb]);
#pragma unroll
    for (int h = 0; h < 16; h++) sbuf[swz((h << 8) | t)] = a[h];
    __syncthreads();
    const int L = lane & 15;
    const int H8 = (lane >> 4) | (w << 1);
#pragma unroll
    for (int m = 0; m < 16; m++) a[m] = sbuf[swz((H8 << 8) | (m << 4) | L)];
#pragma unroll
    for (int qb = 0; qb < 4; qb++) bf_regs(a, qb, sc[4 + qb], ss[4 + qb]);
#pragma unroll
    for (int m = 0; m < 16; m++) sbuf[swz((H8 << 8) | (m << 4) | L)] = a[m];
    __syncthreads();
    const int M = lane & 15;                 // now means q4..7
#pragma unroll
    for (int j = 0; j < 16; j++) a[j] = sbuf[swz((H8 << 8) | (M << 4) | j)];
#pragma unroll
    for (int qb = 0; qb < 4; qb++) bf_regs(a, qb, sc[qb], ss[qb]);

    // ---- measurement ----
    float pt = 0.f, z0 = 0.f, z1 = 0.f, z2 = 0.f, z3 = 0.f;
#pragma unroll
    for (int j = 0; j < 16; j++) {
        const float p = fmaf(a[j].y, a[j].y, a[j].x * a[j].x);
        pt += p;
        z0 += (j & 1) ? -p : p;
        z1 += (j & 2) ? -p : p;
        z2 += (j & 4) ? -p : p;
        z3 += (j & 8) ? -p : p;
    }
    // Walsh-Hadamard over 5 lane bits (q4..8): lane 0 -> total, lane 2^q -> Z
    float v = pt;
#pragma unroll
    for (int stg2 = 0; stg2 < 5; stg2++) {
        const int m = 1 << stg2;
        const float o = __shfl_xor_sync(0xffffffffu, v, m);
        v = (lane & m) ? (o - v) : (v + o);
    }
    float Zl[5];
#pragma unroll
    for (int q = 0; q < 5; q++) Zl[q] = __shfl_sync(0xffffffffu, v, 1 << q);
    const float ptW = __shfl_sync(0xffffffffu, v, 0);
    z0 = wsum(z0); z1 = wsum(z1); z2 = wsum(z2); z3 = wsum(z3);
    if (lane == 0) {
        wred[w][0] = ptW;
#pragma unroll
        for (int q = 0; q < 5; q++) wred[w][1 + q] = Zl[q];
        wred[w][6] = z0; wred[w][7] = z1; wred[w][8] = z2; wred[w][9] = z3;
    }
    __syncthreads();
    if (t < 16) {
        const int q = t;
        float s = 0.f;
        if (q < 4) {
#pragma unroll
            for (int w2 = 0; w2 < 8; w2++) s += wred[w2][6 + q];
        } else if (q < 9) {
#pragma unroll
            for (int w2 = 0; w2 < 8; w2++) s += wred[w2][1 + (q - 4)];
        } else if (q < 12) {
#pragma unroll
            for (int w2 = 0; w2 < 8; w2++)
                s += ((w2 >> (q - 9)) & 1) ? -wred[w2][0] : wred[w2][0];
        } else {
            float tot = 0.f;
#pragma unroll
            for (int w2 = 0; w2 < 8; w2++) tot += wred[w2][0];
            s = ((tile >> (q - 12)) & 1) ? -tot : tot;
        }
        g_partial[sim][tile][q] = s;
    }
}

// ---------------- K4: deterministic reduce, clip, permute to output ----------------
__global__ void k_out(float* __restrict__ out) {
    const int i = blockIdx.x * 64 + threadIdx.x;   // 1024 = 64 sims * 16 qubits
    const int sim = i >> 4, q = i & 15;
    float s = 0.f;
#pragma unroll
    for (int tl = 0; tl < 16; tl++) s += g_partial[sim][tl][q];
    s = fminf(1.0f, fmaxf(-1.0f, s));
    const int bb = sim >> 3, p = sim & 7, h = q >> 2, ww = q & 3;
    out[bb * 128 + h * 32 + p * 4 + ww] = s;
}

// ---------------- launch ----------------
extern "C" void kernel_launch(void* const* d_in, const int* in_sizes, int n_in,
                              void* d_out, int out_size) {
    const float* x     = (const float*)d_in[0];
    const float* wcrz  = (const float*)d_in[1];
    const float* wry   = (const float*)d_in[2];
    const float* scale = (const float*)d_in[3];
    float* out = (float*)d_out;

    k_pass1<<<SIMS * 16, 256>>>(x, wcrz, wry, scale);
    k_pass2<<<SIMS * 16, 256>>>(x, wcrz, wry, scale);
    k_pass3<<<SIMS * 16, 256>>>(wry);
    k_out<<<16, 64>>>(out);
}

// round 14
// speedup vs baseline: 1.0386x; 1.0386x over previous
#include <cuda_runtime.h>
#include <cuda_fp16.h>
#include <math.h>

#define SIMS 64
#define SD 65536            // 2^16 state dim
#define PI_F 3.14159265358979323846f
#define INV_SQRT2 0.70710678118654752440f
#define SCALE 16.0f         // amp scale to keep fp16 in normal range
#define INV_SC2 (1.0f / 256.0f)   // prob descale = 1/SCALE^2

// ---------------- device scratch (static, no allocation) ----------------
__device__ __align__(16) __half2 g_state[SIMS * SD];  // 16 MB (L2-resident)
__device__ float g_partial[SIMS][16][16];             // per-tile Z partials
__device__ unsigned g_ctr = 0;

__device__ __forceinline__ float wsum(float x) {
#pragma unroll
    for (int o = 16; o > 0; o >>= 1) x += __shfl_xor_sync(0xffffffffu, x, o);
    return x;
}

__device__ __forceinline__ void bf_regs(float2 a[16], int qb, float c, float s) {
#pragma unroll
    for (int p = 0; p < 8; p++) {
        const int j0 = ((p >> qb) << (qb + 1)) | (p & ((1 << qb) - 1));
        const int j1 = j0 | (1 << qb);
        const float r0 = c * a[j0].x - s * a[j1].x;
        const float r1 = s * a[j0].x + c * a[j1].x;
        const float i0 = c * a[j0].y - s * a[j1].y;
        const float i1 = s * a[j0].y + c * a[j1].y;
        a[j0].x = r0; a[j1].x = r1; a[j0].y = i0; a[j1].y = i1;
    }
}

__device__ __forceinline__ void bf_shfl(float2 a[16], const float* sc, const float* ss, int lane) {
#pragma unroll
    for (int q = 0; q < 5; q++) {
        const float c = sc[q], s = ss[q];
        const int m = 1 << q;
        const float sgn = (lane & m) ? s : -s;
#pragma unroll
        for (int j = 0; j < 16; j++) {
            const float ox = __shfl_xor_sync(0xffffffffu, a[j].x, m);
            const float oy = __shfl_xor_sync(0xffffffffu, a[j].y, m);
            a[j].x = fmaf(sgn, ox, c * a[j].x);
            a[j].y = fmaf(sgn, oy, c * a[j].y);
        }
    }
}

// ======================================================================
// K1: init product state * D0, RY_A on qubits 0..11 (R8 structure, prep fused).
// Layout L1: t bits 0..7 <-> q0..7 (lane=0..4, warp=5..7), regs j <-> q8..11.
// Layout L1': lane <-> q0..4, warp w <-> q8..10, regs jp: bits0..2 <-> q5..7, bit3 <-> q11.
// ======================================================================
__global__ void __launch_bounds__(256) k_pass1(const float* __restrict__ x,
                                               const float* __restrict__ wcrz,
                                               const float* __restrict__ wry,
                                               const float* __restrict__ scale) {
    const int sim = blockIdx.x >> 4;
    const int tile = blockIdx.x & 15;
    const int t = threadIdx.x, lane = t & 31, w = t >> 5;
    __shared__ float2 sbuf[4096];
    __shared__ float2 A0s[512];          // CRZ L0, controls q0..7 (idx bits q0..8)
    __shared__ float2 sB0[2][16];        // CRZ L0, controls q8..15 ([q0][q8..11]); tile folded
    __shared__ float sc[12], ss[12], sTH[16];
    __shared__ float v0[16], v1[16], hw[32];

    if (t < 32) hw[t] = 0.5f * wcrz[t];
    if (t < 16) {
        const int q = t, bb = sim >> 3, p = sim & 7;
        const float xv = x[bb * 128 + (q >> 2) * 32 + p * 4 + (q & 3)];
        const float enc = tanhf(xv * scale[0]) * PI_F;
        float se, ce; sincosf(enc * 0.5f, &se, &ce);
        v0[q] = (ce - se) * INV_SQRT2;
        v1[q] = (ce + se) * INV_SQRT2;
        if (q < 12) {
            float sA, cA; sincosf((wry[q] + enc) * 0.5f, &sA, &cA);
            sc[q] = cA; ss[q] = sA;
        }
    }
    __syncthreads();
    if (t < 16) {   // TH over q8..15 (bits0..3 = q8..11 = t, tile = q12..15), SCALE folded
        float ph = SCALE;
#pragma unroll
        for (int q = 0; q < 4; q++) {
            ph *= ((t >> q) & 1) ? v1[8 + q] : v0[8 + q];
            ph *= ((tile >> q) & 1) ? v1[12 + q] : v0[12 + q];
        }
        sTH[t] = ph;
    }
    // A0 table: controls q0..7, target q+1 (idx bits 0..8 = q0..8)
    for (int i = t; i < 512; i += 256) {
        float a = 0.f;
#pragma unroll
        for (int q = 0; q < 8; q++)
            if ((i >> q) & 1) a += ((i >> (q + 1)) & 1) ? hw[q] : -hw[q];
        float s, c; sincosf(a, &s, &c);
        A0s[i] = make_float2(c, s);
    }
    // B0 slice: controls q8..15, targets (q+1)&15; [q0][q8..11], tile = q12..15
    if (t < 32) {
        const int b0 = t >> 4, m = t & 15;
        const int i8 = m | (tile << 4);           // bits 0..7 = q8..15
        float a = 0.f;
#pragma unroll
        for (int q = 8; q < 16; q++) {
            if ((i8 >> (q - 8)) & 1) {
                const int tq = (q + 1) & 15;
                const int tb = (tq == 0) ? b0 : ((i8 >> (tq - 8)) & 1);
                a += tb ? hw[q] : -hw[q];
            }
        }
        float s, c; sincosf(a, &s, &c);
        sB0[b0][m] = make_float2(c, s);
    }
    __syncthreads();

    // TL over q0..7 per thread
    float tl = 1.f;
#pragma unroll
    for (int q = 0; q < 8; q++) tl *= ((t >> q) & 1) ? v1[q] : v0[q];

    const float2 pa0 = A0s[t];
    const float2 pa1 = A0s[t | 256];
    const int myb0 = t & 1;
    float2 a[16];
#pragma unroll
    for (int j = 0; j < 16; j++) {
        const float2 pa = (j & 1) ? pa1 : pa0;       // A0 bit8 = q8 = j bit0
        const float2 pb = sB0[myb0][j];
        const float cr = pa.x * pb.x - pa.y * pb.y;
        const float ci = pa.x * pb.y + pa.y * pb.x;
        const float amp = tl * sTH[j];
        a[j] = make_float2(amp * cr, amp * ci);
    }
#pragma unroll
    for (int qb = 0; qb < 4; qb++) bf_regs(a, qb, sc[8 + qb], ss[8 + qb]);
    bf_shfl(a, sc, ss, lane);
#pragma unroll
    for (int j = 0; j < 16; j++) sbuf[(j << 8) | t] = a[j];
    __syncthreads();
    float2 b[16];
#pragma unroll
    for (int jp = 0; jp < 16; jp++) {
        const int oj = w | (jp & 8);
        const int ow = jp & 7;
        b[jp] = sbuf[(oj << 8) | (ow << 5) | lane];
    }
#pragma unroll
    for (int qb = 0; qb < 3; qb++) bf_regs(b, qb, sc[5 + qb], ss[5 + qb]);
    __half2* st = g_state + sim * SD + (tile << 12);
#pragma unroll
    for (int jp = 0; jp < 16; jp++)
        st[lane | ((jp & 7) << 5) | (w << 8) | ((jp & 8) << 8)] = __float22half2_rn(b[jp]);
}

// ======================================================================
// K2: RY_A(12..15), D1 (A1 per-thread + B1 smem), RY_B(12..15). Prep fused.
// ======================================================================
__global__ void __launch_bounds__(256) k_pass2(const float* __restrict__ x,
                                               const float* __restrict__ wcrz,
                                               const float* __restrict__ wry,
                                               const float* __restrict__ scale) {
    const int sim = blockIdx.x >> 4;
    const int blk = blockIdx.x & 15;
    const int t = threadIdx.x;
    const int low12 = (blk << 8) | t;
    __shared__ float2 sB1[64];           // [k][q0..1]
    __shared__ float scA[4], ssA[4], scB[4], ssB[4], sw1[16];
    if (t < 16) sw1[t] = 0.5f * wcrz[16 + t];
    if (t < 4) {
        const int q = 12 + t, bb = sim >> 3, p = sim & 7;
        const float xv = x[bb * 128 + 3 * 32 + p * 4 + t];
        const float enc = tanhf(xv * scale[0]) * PI_F;
        float sA, cA; sincosf((wry[q] + enc) * 0.5f, &sA, &cA);
        scA[t] = cA; ssA[t] = sA;
        float sB, cB; sincosf(wry[16 + q] * 0.5f, &sB, &cB);
        scB[t] = cB; ssB[t] = sB;
    }
    __syncthreads();
    // B1 slice: controls q8..15, targets (q+2)&15; idx bits 0..3=q8..11(blk),
    // 4..7=q12..15(k), 8..9=q0..1
    if (t < 64) {
        const int k = t >> 2, c2 = t & 3;
        const int i = blk | (k << 4) | (c2 << 8);
        float a = 0.f;
#pragma unroll
        for (int q = 8; q < 16; q++)
            if ((i >> (q - 8)) & 1) a += ((i >> (q - 6)) & 1) ? sw1[q] : -sw1[q];
        float s, c; sincosf(a, &s, &c);
        sB1[t] = make_float2(c, s);
    }
    // A1 per thread: controls q0..7, target q+2 (bits 2..9)
    const int i10 = low12 & 1023;
    float aa = 0.f;
#pragma unroll
    for (int q = 0; q < 8; q++)
        if ((i10 >> q) & 1) aa += ((i10 >> (q + 2)) & 1) ? sw1[q] : -sw1[q];
    float pay, pax; sincosf(aa, &pay, &pax);
    __syncthreads();

    __half2* st = g_state + sim * SD;
    float2 a[16];
#pragma unroll
    for (int k = 0; k < 16; k++) a[k] = __half22float2(st[(k << 12) | low12]);
#pragma unroll
    for (int qb = 0; qb < 4; qb++) bf_regs(a, qb, scA[qb], ssA[qb]);
    const int c2 = t & 3;
#pragma unroll
    for (int k = 0; k < 16; k++) {
        const float2 pb = sB1[(k << 2) | c2];
        const float cr = pax * pb.x - pay * pb.y;
        const float ci = pax * pb.y + pay * pb.x;
        const float nx = a[k].x * cr - a[k].y * ci;
        const float ny = a[k].x * ci + a[k].y * cr;
        a[k] = make_float2(nx, ny);
    }
#pragma unroll
    for (int qb = 0; qb < 4; qb++) bf_regs(a, qb, scB[qb], ssB[qb]);
#pragma unroll
    for (int k = 0; k < 16; k++) st[(k << 12) | low12] = __float22half2_rn(a[k]);
}

// ======================================================================
// K3: RY_B qubits 0..11 (R8 structure) + measurement + fused final output.
// ======================================================================
__global__ void __launch_bounds__(256) k_pass3(const float* __restrict__ wry,
                                               float* __restrict__ out) {
    const int sim = blockIdx.x >> 4;
    const int tile = blockIdx.x & 15;
    const int t = threadIdx.x, lane = t & 31, w = t >> 5;
    __shared__ float2 sbuf[4096];
    __shared__ float sc[12], ss[12];
    __shared__ float wred[8][13];
    __shared__ int sflag;
    if (t < 12) {
        float sB, cB; sincosf(wry[16 + t] * 0.5f, &sB, &cB);
        sc[t] = cB; ss[t] = sB;
    }
    __syncthreads();
    // load in layout L1'
    const __half2* stg = g_state + sim * SD + (tile << 12);
    float2 b[16];
#pragma unroll
    for (int jp = 0; jp < 16; jp++)
        b[jp] = __half22float2(stg[lane | ((jp & 7) << 5) | (w << 8) | ((jp & 8) << 8)]);
    // RY_B q5..7 (jp bits 0..2) and q11 (jp bit 3)
#pragma unroll
    for (int qb = 0; qb < 3; qb++) bf_regs(b, qb, sc[5 + qb], ss[5 + qb]);
    bf_regs(b, 3, sc[11], ss[11]);
    bf_shfl(b, sc, ss, lane);                     // q0..4
    // transpose L1' -> L1
#pragma unroll
    for (int jp = 0; jp < 16; jp++)
        sbuf[lane | ((jp & 7) << 5) | (w << 8) | ((jp & 8) << 8)] = b[jp];
    __syncthreads();
    float2 a[16];
#pragma unroll
    for (int j = 0; j < 16; j++) a[j] = sbuf[(j << 8) | t];
#pragma unroll
    for (int qb = 0; qb < 3; qb++) bf_regs(a, qb, sc[8 + qb], ss[8 + qb]);   // q8..10

    // measurement (L1: t<->q0..7, j<->q8..11, tile<->q12..15)
    float pt = 0.f, z8 = 0.f, z9 = 0.f, z10 = 0.f, z11 = 0.f;
#pragma unroll
    for (int j = 0; j < 16; j++) {
        const float p = fmaf(a[j].y, a[j].y, a[j].x * a[j].x);
        pt += p;
        z8  += (j & 1) ? -p : p;
        z9  += (j & 2) ? -p : p;
        z10 += (j & 4) ? -p : p;
        z11 += (j & 8) ? -p : p;
    }
    float v[13];
#pragma unroll
    for (int q = 0; q < 8; q++) v[q] = ((t >> q) & 1) ? -pt : pt;
    v[8] = z8; v[9] = z9; v[10] = z10; v[11] = z11; v[12] = pt;
#pragma unroll
    for (int k = 0; k < 13; k++) v[k] = wsum(v[k]);
    if (lane == 0) {
#pragma unroll
        for (int k = 0; k < 13; k++) wred[w][k] = v[k];
    }
    __syncthreads();
    if (t < 16) {
        float s = 0.f;
        if (t < 12) {
#pragma unroll
            for (int w2 = 0; w2 < 8; w2++) s += wred[w2][t];
        } else {
            float tot = 0.f;
#pragma unroll
            for (int w2 = 0; w2 < 8; w2++) tot += wred[w2][12];
            s = ((tile >> (t - 12)) & 1) ? -tot : tot;
        }
        g_partial[sim][tile][t] = s;
    }
    // ---- last-block fused output ----
    __syncthreads();
    if (t == 0) {
        __threadfence();
        const unsigned old = atomicAdd(&g_ctr, 1u);
        sflag = (old == (unsigned)(SIMS * 16 - 1));
    }
    __syncthreads();
    if (!sflag) return;
    __threadfence();
    for (int it = t; it < SIMS * 16; it += 256) {
        const int sim2 = it >> 4, q = it & 15;
        float s = 0.f;
#pragma unroll
        for (int tl = 0; tl < 16; tl++) s += g_partial[sim2][tl][q];
        s *= INV_SC2;
        s = fminf(1.0f, fmaxf(-1.0f, s));
        const int bb = sim2 >> 3, p = sim2 & 7, h = q >> 2, ww = q & 3;
        out[bb * 128 + h * 32 + p * 4 + ww] = s;
    }
    if (t == 0) g_ctr = 0;    // reset for next graph replay
}

// ---------------- launch ----------------
extern "C" void kernel_launch(void* const* d_in, const int* in_sizes, int n_in,
                              void* d_out, int out_size) {
    const float* x     = (const float*)d_in[0];
    const float* wcrz  = (const float*)d_in[1];
    const float* wry   = (const float*)d_in[2];
    const float* scale = (const float*)d_in[3];
    float* out = (float*)d_out;

    k_pass1<<<SIMS * 16, 256>>>(x, wcrz, wry, scale);
    k_pass2<<<SIMS * 16, 256>>>(x, wcrz, wry, scale);
    k_pass3<<<SIMS * 16, 256>>>(wry, out);
}